// round 1
// baseline (speedup 1.0000x reference)
#include <cuda_runtime.h>
#include <math.h>

// Problem constants (fixed shapes from reference)
#define NQ    16384
#define NK    7933
#define D_IN  1024
#define HD    512
#define THRE_IDX 11469   // NQ - int(0.3*NQ) = 16384 - 4915

// ---------------- scratch (device globals; no allocation allowed) ----------
__device__ float g_qt[NQ * HD];      // tanh(query @ wq^T)      32 MB
__device__ float g_kt[NK * HD];      // tanh(key_x @ wk^T)      16 MB
__device__ float g_s[NK];            // wa[k] / max(||kt_k||,eps)
__device__ float g_v[HD];            // sum_k s[k]*kt[k]
__device__ float g_A1[NQ];
__device__ float g_sorted[NQ];
__device__ float g_thre;
__device__ float g_m;                // softmax max
__device__ float g_Z;                // softmax denom
__device__ float g_z[HD];            // attn-weighted sum of qt rows

// ---------------- init: zero accumulators (graph replays!) -----------------
__global__ void init_kernel() {
    int t = threadIdx.x;
    g_v[t] = 0.f;
    g_z[t] = 0.f;
    if (t == 0) g_Z = 0.f;
}

// ---------------- fp32 GEMM + tanh:  C[m,h] = tanh(sum_d A[m,d]*W[h,d] + b[h])
#define BM 128
#define BN 128
#define BK 16

__global__ __launch_bounds__(256, 2)
void gemm_tanh_kernel(const float* __restrict__ A, const float* __restrict__ W,
                      const float* __restrict__ bias, float* __restrict__ C, int M) {
    __shared__ float As[BK][BM + 4];
    __shared__ float Bs[BK][BN + 4];

    const int bm = blockIdx.y * BM;
    const int bn = blockIdx.x * BN;
    const int tid = threadIdx.x;          // 0..255
    const int tx = tid & 15;              // 0..15 -> cols tx*8..+7
    const int ty = tid >> 4;              // 0..15 -> rows ty*8..+7

    float acc[8][8];
#pragma unroll
    for (int i = 0; i < 8; i++)
#pragma unroll
        for (int j = 0; j < 8; j++) acc[i][j] = 0.f;

    for (int k0 = 0; k0 < D_IN; k0 += BK) {
        // load A tile (BM x BK) : 512 float4 loads, 2 per thread
#pragma unroll
        for (int i = 0; i < 2; i++) {
            int idx = tid + i * 256;          // 0..511
            int r   = idx >> 2;               // 0..127
            int kq  = (idx & 3) * 4;          // 0,4,8,12
            int gr  = bm + r;
            float4 va = make_float4(0.f, 0.f, 0.f, 0.f);
            if (gr < M) va = *(const float4*)(A + (size_t)gr * D_IN + k0 + kq);
            As[kq + 0][r] = va.x;
            As[kq + 1][r] = va.y;
            As[kq + 2][r] = va.z;
            As[kq + 3][r] = va.w;
        }
        // load W tile (BN x BK); W is [HD, D_IN], HD=512 divisible by BN
#pragma unroll
        for (int i = 0; i < 2; i++) {
            int idx = tid + i * 256;
            int r   = idx >> 2;
            int kq  = (idx & 3) * 4;
            float4 vb = *(const float4*)(W + (size_t)(bn + r) * D_IN + k0 + kq);
            Bs[kq + 0][r] = vb.x;
            Bs[kq + 1][r] = vb.y;
            Bs[kq + 2][r] = vb.z;
            Bs[kq + 3][r] = vb.w;
        }
        __syncthreads();

#pragma unroll
        for (int kk = 0; kk < BK; kk++) {
            float af[8], bf[8];
#pragma unroll
            for (int i = 0; i < 8; i++) af[i] = As[kk][ty * 8 + i];
#pragma unroll
            for (int j = 0; j < 8; j++) bf[j] = Bs[kk][tx * 8 + j];
#pragma unroll
            for (int i = 0; i < 8; i++)
#pragma unroll
                for (int j = 0; j < 8; j++)
                    acc[i][j] = fmaf(af[i], bf[j], acc[i][j]);
        }
        __syncthreads();
    }

    // epilogue: bias + tanh
#pragma unroll
    for (int i = 0; i < 8; i++) {
        int gr = bm + ty * 8 + i;
        if (gr < M) {
#pragma unroll
            for (int j = 0; j < 8; j++) {
                int gc = bn + tx * 8 + j;
                C[(size_t)gr * HD + gc] = tanhf(acc[i][j] + bias[gc]);
            }
        }
    }
}

// ---------------- per-row scale for k: s[k] = wa[k] / max(||kt_k||, 1e-12)
__global__ void k_scale_kernel(const float* __restrict__ wa_w) {
    int row  = blockIdx.x * 8 + (threadIdx.x >> 5);
    int lane = threadIdx.x & 31;
    if (row >= NK) return;
    const float* kr = g_kt + (size_t)row * HD;
    float ss = 0.f;
#pragma unroll
    for (int i = lane; i < HD; i += 32) { float x = kr[i]; ss = fmaf(x, x, ss); }
#pragma unroll
    for (int o = 16; o > 0; o >>= 1) ss += __shfl_xor_sync(0xffffffffu, ss, o);
    if (lane == 0) g_s[row] = wa_w[row] / fmaxf(sqrtf(ss), 1e-12f);
}

// ---------------- v[h] = sum_k s[k] * kt[k][h]
__global__ void v_accum_kernel() {
    int h  = blockIdx.x * 256 + threadIdx.x;    // blockIdx.x in {0,1}
    int k0 = blockIdx.y * 256;
    int k1 = min(k0 + 256, NK);
    float acc = 0.f;
    for (int k = k0; k < k1; k++)
        acc = fmaf(g_s[k], g_kt[(size_t)k * HD + h], acc);
    atomicAdd(&g_v[h], acc);
}

// ---------------- A1[q] = dot(qt_q, v)/max(||qt_q||,eps) + wa_b
__global__ void a1_kernel(const float* __restrict__ wa_b) {
    int row  = blockIdx.x * 8 + (threadIdx.x >> 5);
    int lane = threadIdx.x & 31;
    const float* qr = g_qt + (size_t)row * HD;
    float ss = 0.f, dot = 0.f;
#pragma unroll
    for (int i = lane; i < HD; i += 32) {
        float x = qr[i];
        ss  = fmaf(x, x, ss);
        dot = fmaf(x, g_v[i], dot);
    }
#pragma unroll
    for (int o = 16; o > 0; o >>= 1) {
        ss  += __shfl_xor_sync(0xffffffffu, ss,  o);
        dot += __shfl_xor_sync(0xffffffffu, dot, o);
    }
    if (lane == 0)
        g_A1[row] = dot / fmaxf(sqrtf(ss), 1e-12f) + wa_b[0];
}

// ---------------- single-block bitonic sort of A1 (16384 = 2^14) -----------
__global__ void sort_kernel() {
    for (int i = threadIdx.x; i < NQ; i += blockDim.x) g_sorted[i] = g_A1[i];
    __syncthreads();
    for (int size = 2; size <= NQ; size <<= 1) {
        for (int stride = size >> 1; stride > 0; stride >>= 1) {
            for (int i = threadIdx.x; i < NQ; i += blockDim.x) {
                int j = i ^ stride;
                if (j > i) {
                    float a = g_sorted[i];
                    float b = g_sorted[j];
                    bool up = ((i & size) == 0);
                    if ((a > b) == up) { g_sorted[i] = b; g_sorted[j] = a; }
                }
            }
            __syncthreads();
        }
    }
    if (threadIdx.x == 0) {
        g_thre = g_sorted[THRE_IDX];
        g_m    = fmaxf(g_sorted[NQ - 1], 0.f);   // zeros participate in softmax
    }
}

// ---------------- softmax denominator --------------------------------------
__global__ void zdenom_kernel() {
    __shared__ float red[8];
    int q = blockIdx.x * 256 + threadIdx.x;
    float a = g_A1[q];
    float t = (a > g_thre) ? a : 0.f;
    float e = expf(t - g_m);
#pragma unroll
    for (int o = 16; o > 0; o >>= 1) e += __shfl_xor_sync(0xffffffffu, e, o);
    int lane = threadIdx.x & 31, w = threadIdx.x >> 5;
    if (lane == 0) red[w] = e;
    __syncthreads();
    if (w == 0) {
        float s = (lane < 8) ? red[lane] : 0.f;
#pragma unroll
        for (int o = 4; o > 0; o >>= 1) s += __shfl_xor_sync(0xffffffffu, s, o);
        if (lane == 0) atomicAdd(&g_Z, s);
    }
}

// ---------------- attn values -> output ------------------------------------
__global__ void attn_kernel(float* __restrict__ out) {
    int q = blockIdx.x * 256 + threadIdx.x;
    float a = g_A1[q];
    float t = (a > g_thre) ? a : 0.f;
    out[1 + q] = expf(t - g_m) / g_Z;
}

// ---------------- z[h] = sum_q attn[q]*qt[q][h] -----------------------------
__global__ void z_accum_kernel(const float* __restrict__ out) {
    int h  = blockIdx.x * 128 + threadIdx.x;   // blockIdx.x in 0..3
    int q0 = blockIdx.y * 256;
    float acc = 0.f;
    for (int q = q0; q < q0 + 256; q++)
        acc = fmaf(out[1 + q], g_qt[(size_t)q * HD + h], acc);
    atomicAdd(&g_z[h], acc);
}

// ---------------- final classifier ------------------------------------------
__global__ void final_kernel(const float* __restrict__ cls_w,
                             const float* __restrict__ cls_b,
                             float* __restrict__ out) {
    __shared__ float red[16];
    int t = threadIdx.x;                  // 512 threads
    float p = g_z[t] * cls_w[t];
#pragma unroll
    for (int o = 16; o > 0; o >>= 1) p += __shfl_xor_sync(0xffffffffu, p, o);
    int lane = t & 31, w = t >> 5;
    if (lane == 0) red[w] = p;
    __syncthreads();
    if (w == 0) {
        float s = (lane < 16) ? red[lane] : 0.f;
#pragma unroll
        for (int o = 8; o > 0; o >>= 1) s += __shfl_xor_sync(0xffffffffu, s, o);
        if (lane == 0) out[0] = s + cls_b[0];
    }
}

// ---------------- launch ----------------------------------------------------
extern "C" void kernel_launch(void* const* d_in, const int* in_sizes, int n_in,
                              void* d_out, int out_size) {
    const float* query = (const float*)d_in[0];   // [1,NQ,D_IN]
    const float* key_x = (const float*)d_in[1];   // [1,NK,D_IN]
    const float* wq_w  = (const float*)d_in[2];   // [HD,D_IN]
    const float* wq_b  = (const float*)d_in[3];   // [HD]
    const float* wk_w  = (const float*)d_in[4];   // [HD,D_IN]
    const float* wk_b  = (const float*)d_in[5];   // [HD]
    const float* wa_w  = (const float*)d_in[6];   // [1,NK]
    const float* wa_b  = (const float*)d_in[7];   // [1]
    const float* cls_w = (const float*)d_in[8];   // [1,HD]
    const float* cls_b = (const float*)d_in[9];   // [1]
    float* out = (float*)d_out;                   // [0]=y_prob, [1..NQ]=attn

    float* qt; cudaGetSymbolAddress((void**)&qt, g_qt);
    float* kt; cudaGetSymbolAddress((void**)&kt, g_kt);

    init_kernel<<<1, 512>>>();

    dim3 gq(HD / BN, (NQ + BM - 1) / BM);   // (4,128)
    gemm_tanh_kernel<<<gq, 256>>>(query, wq_w, wq_b, qt, NQ);

    dim3 gk(HD / BN, (NK + BM - 1) / BM);   // (4,62)
    gemm_tanh_kernel<<<gk, 256>>>(key_x, wk_w, wk_b, kt, NK);

    k_scale_kernel<<<(NK + 7) / 8, 256>>>(wa_w);
    v_accum_kernel<<<dim3(2, (NK + 255) / 256), 256>>>();
    a1_kernel<<<NQ / 8, 256>>>(wa_b);
    sort_kernel<<<1, 1024>>>();
    zdenom_kernel<<<NQ / 256, 256>>>();
    attn_kernel<<<NQ / 256, 256>>>(out);
    z_accum_kernel<<<dim3(4, NQ / 256), 128>>>(out);
    final_kernel<<<1, 512>>>(cls_w, cls_b, out);
}

// round 3
// speedup vs baseline: 3.3898x; 3.3898x over previous
#include <cuda_runtime.h>
#include <cuda_bf16.h>
#include <math.h>
#include <stdint.h>

// Problem constants (fixed shapes from reference)
#define NQ    16384
#define NK    7933
#define D_IN  1024
#define HD    512
#define THRE_IDX 11469   // NQ - int(0.3*NQ)

// ---------------------------------------------------------------------------
// Scratch (device globals)
// ---------------------------------------------------------------------------
__device__ float g_qt[NQ * HD];      // tanh(query @ wq^T)
__device__ float g_kt[NK * HD];      // tanh(key_x @ wk^T)
__device__ float g_s[NK];
__device__ float g_v[HD];
__device__ float g_A1[NQ];
__device__ float g_thre;
__device__ float g_m;
__device__ float g_Z;
__device__ float g_z[HD];

// ---------------------------------------------------------------------------
__global__ void init_kernel() {
    int t = threadIdx.x;
    g_v[t] = 0.f;
    g_z[t] = 0.f;
    if (t == 0) g_Z = 0.f;
}

// ---------------------------------------------------------------------------
// mma.sync bf16 GEMM + tanh:  C[m,h] = tanh(sum_d A[m,d]*W[h,d] + b[h])
// hi/lo fp32->bf16 split, 3 products (AhWh + AhWl + AlWh), fp32 accumulate.
// Block 128x128, 8 warps (warp tile 32x64), K-chunk 32 fp32.
// ---------------------------------------------------------------------------
__device__ __forceinline__ uint32_t smem_u32(const void* p) {
    uint32_t a;
    asm("{ .reg .u64 t; cvta.to.shared.u64 t, %1; cvt.u32.u64 %0, t; }" : "=r"(a) : "l"(p));
    return a;
}
__device__ __forceinline__ void ldm_x4(uint32_t* r, uint32_t addr) {
    asm volatile("ldmatrix.sync.aligned.m8n8.x4.shared.b16 {%0,%1,%2,%3}, [%4];"
                 : "=r"(r[0]), "=r"(r[1]), "=r"(r[2]), "=r"(r[3]) : "r"(addr));
}
__device__ __forceinline__ void mma_bf16(float* d, const uint32_t* a, const uint32_t* b) {
    asm volatile(
        "mma.sync.aligned.m16n8k16.row.col.f32.bf16.bf16.f32 "
        "{%0,%1,%2,%3}, {%4,%5,%6,%7}, {%8,%9}, {%0,%1,%2,%3};"
        : "+f"(d[0]), "+f"(d[1]), "+f"(d[2]), "+f"(d[3])
        : "r"(a[0]), "r"(a[1]), "r"(a[2]), "r"(a[3]), "r"(b[0]), "r"(b[1]));
}

#define LDS 40                    // bf16 stride per 32-wide row (+8 pad)
#define NCH (D_IN / 32)           // 32 K-chunks

__global__ __launch_bounds__(256)
void gemm_tc_kernel(const float* __restrict__ query, const float* __restrict__ wq_w,
                    const float* __restrict__ wq_b,
                    const float* __restrict__ key_x, const float* __restrict__ wk_w,
                    const float* __restrict__ wk_b)
{
    // smem: 4 tiles of [128][40] bf16 = 10240 B each
    __shared__ __align__(16) char sm[40960];
    const int AH = 0, AL = 10240, WH = 20480, WL = 30720;

    const int tid = threadIdx.x;
    const int wid = tid >> 5;
    const int lane = tid & 31;
    const int by = blockIdx.y;

    const float* Ag; const float* Wg; const float* bias; float* C; int M, bm;
    if (by < 128) {
        Ag = query; Wg = wq_w; bias = wq_b; C = g_qt; M = NQ; bm = by * 128;
    } else {
        Ag = key_x; Wg = wk_w; bias = wk_b; C = g_kt; M = NK; bm = (by - 128) * 128;
    }
    const int bn = blockIdx.x * 128;

    const uint32_t sAH = smem_u32(sm) + AH;
    const uint32_t sAL = smem_u32(sm) + AL;
    const uint32_t sWH = smem_u32(sm) + WH;
    const uint32_t sWL = smem_u32(sm) + WL;

    const int warp_m = (wid & 3) * 32;
    const int warp_n = (wid >> 2) * 64;

    float acc[2][8][4];
#pragma unroll
    for (int mt = 0; mt < 2; mt++)
#pragma unroll
        for (int nt = 0; nt < 8; nt++)
#pragma unroll
            for (int i = 0; i < 4; i++) acc[mt][nt][i] = 0.f;

    // staging registers (prefetch one chunk ahead)
    float4 ra[4], rw[4];
    {
#pragma unroll
        for (int j = 0; j < 4; j++) {
            int idx = tid + j * 256;      // 0..1023 float4 granules (128 rows x 8)
            int r = idx >> 3, q = idx & 7;
            int gr = bm + r;
            ra[j] = (gr < M) ? *(const float4*)(Ag + (size_t)gr * D_IN + q * 4)
                             : make_float4(0.f, 0.f, 0.f, 0.f);
            rw[j] = *(const float4*)(Wg + (size_t)(bn + r) * D_IN + q * 4);
        }
    }

    for (int c = 0; c < NCH; c++) {
        // ---- store staged chunk into smem as bf16 hi/lo ----
#pragma unroll
        for (int j = 0; j < 4; j++) {
            int idx = tid + j * 256;
            int r = idx >> 3, q = idx & 7;
            uint32_t boff = (uint32_t)(r * LDS + q * 4) * 2;
            {
                float4 v = ra[j];
                __nv_bfloat162 h01 = __floats2bfloat162_rn(v.x, v.y);
                __nv_bfloat162 h23 = __floats2bfloat162_rn(v.z, v.w);
                __nv_bfloat162 l01 = __floats2bfloat162_rn(v.x - __bfloat162float(h01.x),
                                                           v.y - __bfloat162float(h01.y));
                __nv_bfloat162 l23 = __floats2bfloat162_rn(v.z - __bfloat162float(h23.x),
                                                           v.w - __bfloat162float(h23.y));
                *(uint2*)(sm + AH + boff) = make_uint2(*(uint32_t*)&h01, *(uint32_t*)&h23);
                *(uint2*)(sm + AL + boff) = make_uint2(*(uint32_t*)&l01, *(uint32_t*)&l23);
            }
            {
                float4 v = rw[j];
                __nv_bfloat162 h01 = __floats2bfloat162_rn(v.x, v.y);
                __nv_bfloat162 h23 = __floats2bfloat162_rn(v.z, v.w);
                __nv_bfloat162 l01 = __floats2bfloat162_rn(v.x - __bfloat162float(h01.x),
                                                           v.y - __bfloat162float(h01.y));
                __nv_bfloat162 l23 = __floats2bfloat162_rn(v.z - __bfloat162float(h23.x),
                                                           v.w - __bfloat162float(h23.y));
                *(uint2*)(sm + WH + boff) = make_uint2(*(uint32_t*)&h01, *(uint32_t*)&h23);
                *(uint2*)(sm + WL + boff) = make_uint2(*(uint32_t*)&l01, *(uint32_t*)&l23);
            }
        }
        __syncthreads();

        // ---- prefetch next chunk (latency hidden under MMA work) ----
        if (c + 1 < NCH) {
            int k0 = (c + 1) * 32;
#pragma unroll
            for (int j = 0; j < 4; j++) {
                int idx = tid + j * 256;
                int r = idx >> 3, q = idx & 7;
                int gr = bm + r;
                ra[j] = (gr < M) ? *(const float4*)(Ag + (size_t)gr * D_IN + k0 + q * 4)
                                 : make_float4(0.f, 0.f, 0.f, 0.f);
                rw[j] = *(const float4*)(Wg + (size_t)(bn + r) * D_IN + k0 + q * 4);
            }
        }

        // ---- compute: 2 k16 steps ----
#pragma unroll
        for (int kk = 0; kk < 2; kk++) {
            uint32_t ah[2][4], al[2][4], bh[4][4], bl[4][4];
#pragma unroll
            for (int mt = 0; mt < 2; mt++) {
                int r = warp_m + mt * 16 + (lane & 15);
                int cc = kk * 16 + (lane >> 4) * 8;
                uint32_t off = (uint32_t)(r * LDS + cc) * 2;
                ldm_x4(ah[mt], sAH + off);
                ldm_x4(al[mt], sAL + off);
            }
#pragma unroll
            for (int nt2 = 0; nt2 < 4; nt2++) {
                int r = warp_n + nt2 * 16 + ((lane >> 4) ? 8 : 0) + (lane & 7);
                int cc = kk * 16 + ((lane >> 3) & 1) * 8;
                uint32_t off = (uint32_t)(r * LDS + cc) * 2;
                ldm_x4(bh[nt2], sWH + off);
                ldm_x4(bl[nt2], sWL + off);
            }
#pragma unroll
            for (int mt = 0; mt < 2; mt++)
#pragma unroll
                for (int nt = 0; nt < 8; nt++) {
                    const uint32_t* pbh = &bh[nt >> 1][(nt & 1) * 2];
                    const uint32_t* pbl = &bl[nt >> 1][(nt & 1) * 2];
                    mma_bf16(acc[mt][nt], ah[mt], pbh);
                    mma_bf16(acc[mt][nt], ah[mt], pbl);
                    mma_bf16(acc[mt][nt], al[mt], pbh);
                }
        }
        __syncthreads();
    }

    // ---- epilogue: bias + tanh ----
#pragma unroll
    for (int mt = 0; mt < 2; mt++) {
        int r0 = bm + warp_m + mt * 16 + (lane >> 2);
#pragma unroll
        for (int nt = 0; nt < 8; nt++) {
            int gc = bn + warp_n + nt * 8 + (lane & 3) * 2;
            float b0 = bias[gc], b1 = bias[gc + 1];
            if (r0 < M) {
                C[(size_t)r0 * HD + gc]     = tanhf(acc[mt][nt][0] + b0);
                C[(size_t)r0 * HD + gc + 1] = tanhf(acc[mt][nt][1] + b1);
            }
            if (r0 + 8 < M) {
                C[(size_t)(r0 + 8) * HD + gc]     = tanhf(acc[mt][nt][2] + b0);
                C[(size_t)(r0 + 8) * HD + gc + 1] = tanhf(acc[mt][nt][3] + b1);
            }
        }
    }
}

// ---------------------------------------------------------------------------
// per-row scale for k: s[k] = wa[k] / max(||kt_k||, 1e-12)
__global__ void k_scale_kernel(const float* __restrict__ wa_w) {
    int row  = blockIdx.x * 8 + (threadIdx.x >> 5);
    int lane = threadIdx.x & 31;
    if (row >= NK) return;
    const float* kr = g_kt + (size_t)row * HD;
    float ss = 0.f;
#pragma unroll
    for (int i = lane; i < HD; i += 32) { float x = kr[i]; ss = fmaf(x, x, ss); }
#pragma unroll
    for (int o = 16; o > 0; o >>= 1) ss += __shfl_xor_sync(0xffffffffu, ss, o);
    if (lane == 0) g_s[row] = wa_w[row] / fmaxf(sqrtf(ss), 1e-12f);
}

// v[h] = sum_k s[k] * kt[k][h]
__global__ void v_accum_kernel() {
    int h  = blockIdx.x * 256 + threadIdx.x;
    int k0 = blockIdx.y * 256;
    int k1 = min(k0 + 256, NK);
    float acc = 0.f;
    for (int k = k0; k < k1; k++)
        acc = fmaf(g_s[k], g_kt[(size_t)k * HD + h], acc);
    atomicAdd(&g_v[h], acc);
}

// A1[q] = dot(qt_q, v)/max(||qt_q||,eps) + wa_b
__global__ void a1_kernel(const float* __restrict__ wa_b) {
    int row  = blockIdx.x * 8 + (threadIdx.x >> 5);
    int lane = threadIdx.x & 31;
    const float* qr = g_qt + (size_t)row * HD;
    float ss = 0.f, dot = 0.f;
#pragma unroll
    for (int i = lane; i < HD; i += 32) {
        float x = qr[i];
        ss  = fmaf(x, x, ss);
        dot = fmaf(x, g_v[i], dot);
    }
#pragma unroll
    for (int o = 16; o > 0; o >>= 1) {
        ss  += __shfl_xor_sync(0xffffffffu, ss,  o);
        dot += __shfl_xor_sync(0xffffffffu, dot, o);
    }
    if (lane == 0)
        g_A1[row] = dot / fmaxf(sqrtf(ss), 1e-12f) + wa_b[0];
}

// ---------------------------------------------------------------------------
// Exact k-th order statistic via 3-level radix select + global max.
// ---------------------------------------------------------------------------
__device__ __forceinline__ uint32_t f2ord(float f) {
    uint32_t u = __float_as_uint(f);
    return u ^ ((u >> 31) ? 0xFFFFFFFFu : 0x80000000u);
}
__device__ __forceinline__ float ord2f(uint32_t u) {
    u ^= ((u >> 31) ? 0x80000000u : 0xFFFFFFFFu);
    return __uint_as_float(u);
}

__global__ void select_kernel() {
    __shared__ uint32_t hist[2048];
    __shared__ uint32_t wred[32];
    __shared__ uint32_t s_bin, s_base;
    __shared__ float s_max;
    const int t = threadIdx.x;
    const int lane = t & 31, w = t >> 5;

    float mx = -INFINITY;
    for (int i = t; i < NQ; i += 1024) mx = fmaxf(mx, g_A1[i]);
#pragma unroll
    for (int o = 16; o > 0; o >>= 1) mx = fmaxf(mx, __shfl_xor_sync(0xffffffffu, mx, o));
    if (lane == 0) wred[w] = __float_as_uint(mx);
    __syncthreads();
    if (w == 0) {
        float m = __uint_as_float(wred[lane]);
#pragma unroll
        for (int o = 16; o > 0; o >>= 1) m = fmaxf(m, __shfl_xor_sync(0xffffffffu, m, o));
        if (lane == 0) s_max = m;
    }
    __syncthreads();

    uint32_t k = THRE_IDX;
    uint32_t prefix = 0, pmask = 0;
    const int shifts[3] = {21, 10, 0};
    const uint32_t widths[3] = {2048, 2048, 1024};

    for (int lev = 0; lev < 3; lev++) {
        const int sh = shifts[lev];
        const uint32_t width = widths[lev];
        const uint32_t bmask = width - 1;
        hist[t] = 0; hist[t + 1024] = 0;
        __syncthreads();
        for (int i = t; i < NQ; i += 1024) {
            uint32_t key = f2ord(g_A1[i]);
            if ((key & pmask) == prefix)
                atomicAdd(&hist[(key >> sh) & bmask], 1u);
        }
        __syncthreads();
        uint32_t c0 = (2u * t     < width) ? hist[2 * t]     : 0u;
        uint32_t c1 = (2u * t + 1 < width) ? hist[2 * t + 1] : 0u;
        uint32_t tsum = c0 + c1;
        uint32_t inc = tsum;
#pragma unroll
        for (int o = 1; o < 32; o <<= 1) {
            uint32_t v = __shfl_up_sync(0xffffffffu, inc, o);
            if (lane >= o) inc += v;
        }
        if (lane == 31) wred[w] = inc;
        __syncthreads();
        if (w == 0) {
            uint32_t v = wred[lane];
            uint32_t winc = v;
#pragma unroll
            for (int o = 1; o < 32; o <<= 1) {
                uint32_t x = __shfl_up_sync(0xffffffffu, winc, o);
                if (lane >= o) winc += x;
            }
            wred[lane] = winc - v;   // exclusive
        }
        __syncthreads();
        uint32_t ex = wred[w] + (inc - tsum);
        if (k >= ex && k < ex + c0)             { s_bin = 2 * t;     s_base = ex; }
        else if (k >= ex + c0 && k < ex + tsum) { s_bin = 2 * t + 1; s_base = ex + c0; }
        __syncthreads();
        uint32_t bin = s_bin;
        k -= s_base;
        prefix |= (bin << sh);
        pmask  |= (bmask << sh);
        __syncthreads();
    }
    if (t == 0) {
        g_thre = ord2f(prefix);
        g_m = fmaxf(s_max, 0.f);
    }
}

// ---------------------------------------------------------------------------
__global__ void zdenom_kernel() {
    __shared__ float red[8];
    int q = blockIdx.x * 256 + threadIdx.x;
    float a = g_A1[q];
    float tt = (a > g_thre) ? a : 0.f;
    float e = expf(tt - g_m);
#pragma unroll
    for (int o = 16; o > 0; o >>= 1) e += __shfl_xor_sync(0xffffffffu, e, o);
    int lane = threadIdx.x & 31, w = threadIdx.x >> 5;
    if (lane == 0) red[w] = e;
    __syncthreads();
    if (w == 0) {
        float s = (lane < 8) ? red[lane] : 0.f;
#pragma unroll
        for (int o = 4; o > 0; o >>= 1) s += __shfl_xor_sync(0xffffffffu, s, o);
        if (lane == 0) atomicAdd(&g_Z, s);
    }
}

__global__ void attn_kernel(float* __restrict__ out) {
    int q = blockIdx.x * 256 + threadIdx.x;
    float a = g_A1[q];
    float tt = (a > g_thre) ? a : 0.f;
    out[1 + q] = expf(tt - g_m) / g_Z;
}

__global__ void z_accum_kernel(const float* __restrict__ out) {
    int h  = blockIdx.x * 128 + threadIdx.x;
    int q0 = blockIdx.y * 256;
    float acc = 0.f;
    for (int q = q0; q < q0 + 256; q++)
        acc = fmaf(out[1 + q], g_qt[(size_t)q * HD + h], acc);
    atomicAdd(&g_z[h], acc);
}

__global__ void final_kernel(const float* __restrict__ cls_w,
                             const float* __restrict__ cls_b,
                             float* __restrict__ out) {
    __shared__ float red[16];
    int t = threadIdx.x;
    float p = g_z[t] * cls_w[t];
#pragma unroll
    for (int o = 16; o > 0; o >>= 1) p += __shfl_xor_sync(0xffffffffu, p, o);
    int lane = t & 31, w = t >> 5;
    if (lane == 0) red[w] = p;
    __syncthreads();
    if (w == 0) {
        float s = (lane < 16) ? red[lane] : 0.f;
#pragma unroll
        for (int o = 8; o > 0; o >>= 1) s += __shfl_xor_sync(0xffffffffu, s, o);
        if (lane == 0) out[0] = s + cls_b[0];
    }
}

// ---------------------------------------------------------------------------
extern "C" void kernel_launch(void* const* d_in, const int* in_sizes, int n_in,
                              void* d_out, int out_size) {
    const float* query = (const float*)d_in[0];
    const float* key_x = (const float*)d_in[1];
    const float* wq_w  = (const float*)d_in[2];
    const float* wq_b  = (const float*)d_in[3];
    const float* wk_w  = (const float*)d_in[4];
    const float* wk_b  = (const float*)d_in[5];
    const float* wa_w  = (const float*)d_in[6];
    const float* wa_b  = (const float*)d_in[7];
    const float* cls_w = (const float*)d_in[8];
    const float* cls_b = (const float*)d_in[9];
    float* out = (float*)d_out;

    init_kernel<<<1, 512>>>();

    // Fused q+k projection GEMMs: grid y = 128 (q) + 62 (k) blocks
    dim3 gg(HD / 128, 128 + (NK + 127) / 128);
    gemm_tc_kernel<<<gg, 256>>>(query, wq_w, wq_b, key_x, wk_w, wk_b);

    k_scale_kernel<<<(NK + 7) / 8, 256>>>(wa_w);
    v_accum_kernel<<<dim3(2, (NK + 255) / 256), 256>>>();
    a1_kernel<<<NQ / 8, 256>>>(wa_b);
    select_kernel<<<1, 1024>>>();
    zdenom_kernel<<<NQ / 256, 256>>>();
    attn_kernel<<<NQ / 256, 256>>>(out);
    z_accum_kernel<<<dim3(4, NQ / 256), 128>>>(out);
    final_kernel<<<1, 512>>>(cls_w, cls_b, out);
}

// round 4
// speedup vs baseline: 3.5796x; 1.0560x over previous
#include <cuda_runtime.h>
#include <cuda_bf16.h>
#include <math.h>
#include <stdint.h>

// Problem constants (fixed shapes from reference)
#define NQ    16384
#define NK    7933
#define D_IN  1024
#define HD    512
#define THRE_IDX 11469   // NQ - int(0.3*NQ)

// ---------------------------------------------------------------------------
// Scratch (device globals)
// ---------------------------------------------------------------------------
__device__ __align__(16) float g_qt[NQ * HD];   // tanh(query @ wq^T)
__device__ __align__(16) float g_kt[NK * HD];   // tanh(key_x @ wk^T)
__device__ float g_qn2[NQ];          // row sum-of-squares of g_qt
__device__ float g_kn2[NK];          // row sum-of-squares of g_kt
__device__ float g_s[NK];
__device__ __align__(16) float g_v[HD];
__device__ float g_A1[NQ];
__device__ float g_thre;
__device__ float g_m;
__device__ float g_Z;
__device__ float g_z[HD];

// ---------------------------------------------------------------------------
__global__ void init_kernel() {
    int i = blockIdx.x * 256 + threadIdx.x;
    if (i < NQ) g_qn2[i] = 0.f;
    if (i < NK) g_kn2[i] = 0.f;
    if (i < HD) { g_v[i] = 0.f; g_z[i] = 0.f; }
    if (i == 0) g_Z = 0.f;
}

// ---------------------------------------------------------------------------
// mma.sync bf16 GEMM + tanh + fused row-norm accumulation.
// hi/lo fp32->bf16 split, 3 products, fp32 accumulate.
// Block 128x128, 8 warps (warp tile 32x64), K-chunk 32 fp32, double-buffered.
// ---------------------------------------------------------------------------
__device__ __forceinline__ uint32_t smem_u32(const void* p) {
    uint32_t a;
    asm("{ .reg .u64 t; cvta.to.shared.u64 t, %1; cvt.u32.u64 %0, t; }" : "=r"(a) : "l"(p));
    return a;
}
__device__ __forceinline__ void ldm_x4(uint32_t* r, uint32_t addr) {
    asm volatile("ldmatrix.sync.aligned.m8n8.x4.shared.b16 {%0,%1,%2,%3}, [%4];"
                 : "=r"(r[0]), "=r"(r[1]), "=r"(r[2]), "=r"(r[3]) : "r"(addr));
}
__device__ __forceinline__ void mma_bf16(float* d, const uint32_t* a, const uint32_t* b) {
    asm volatile(
        "mma.sync.aligned.m16n8k16.row.col.f32.bf16.bf16.f32 "
        "{%0,%1,%2,%3}, {%4,%5,%6,%7}, {%8,%9}, {%0,%1,%2,%3};"
        : "+f"(d[0]), "+f"(d[1]), "+f"(d[2]), "+f"(d[3])
        : "r"(a[0]), "r"(a[1]), "r"(a[2]), "r"(a[3]), "r"(b[0]), "r"(b[1]));
}

#define LDS 40                    // bf16 stride per 32-wide row (+8 pad) — conflict-free ldmatrix
#define NCH (D_IN / 32)           // 32 K-chunks
#define BUF_BYTES 40960           // 4 tiles of [128][40] bf16
#define GEMM_SMEM (2 * BUF_BYTES) // 81920

__global__ __launch_bounds__(256)
void gemm_tc_kernel(const float* __restrict__ query, const float* __restrict__ wq_w,
                    const float* __restrict__ wq_b,
                    const float* __restrict__ key_x, const float* __restrict__ wk_w,
                    const float* __restrict__ wk_b)
{
    extern __shared__ __align__(16) char sm[];
    const int AH = 0, AL = 10240, WH = 20480, WL = 30720;

    const int tid = threadIdx.x;
    const int wid = tid >> 5;
    const int lane = tid & 31;
    const int by = blockIdx.y;

    const float* Ag; const float* Wg; const float* bias; float* C; float* N2; int M, bm;
    if (by < 128) {
        Ag = query; Wg = wq_w; bias = wq_b; C = g_qt; N2 = g_qn2; M = NQ; bm = by * 128;
    } else {
        Ag = key_x; Wg = wk_w; bias = wk_b; C = g_kt; N2 = g_kn2; M = NK; bm = (by - 128) * 128;
    }
    const int bn = blockIdx.x * 128;

    const uint32_t smb = smem_u32(sm);
    const int warp_m = (wid & 3) * 32;
    const int warp_n = (wid >> 2) * 64;

    float acc[2][8][4];
#pragma unroll
    for (int mt = 0; mt < 2; mt++)
#pragma unroll
        for (int nt = 0; nt < 8; nt++)
#pragma unroll
            for (int i = 0; i < 4; i++) acc[mt][nt][i] = 0.f;

    // staging registers
    float4 ra[4], rw[4];
#pragma unroll
    for (int j = 0; j < 4; j++) {
        int idx = tid + j * 256;
        int r = idx >> 3, q = idx & 7;
        int gr = bm + r;
        ra[j] = (gr < M) ? *(const float4*)(Ag + (size_t)gr * D_IN + q * 4)
                         : make_float4(0.f, 0.f, 0.f, 0.f);
        rw[j] = *(const float4*)(Wg + (size_t)(bn + r) * D_IN + q * 4);
    }

    for (int c = 0; c < NCH; c++) {
        const int base = (c & 1) * BUF_BYTES;
        // ---- convert + store staged chunk into buffer c&1 ----
#pragma unroll
        for (int j = 0; j < 4; j++) {
            int idx = tid + j * 256;
            int r = idx >> 3, q = idx & 7;
            uint32_t boff = (uint32_t)(r * LDS + q * 4) * 2;
            {
                float4 v = ra[j];
                __nv_bfloat162 h01 = __floats2bfloat162_rn(v.x, v.y);
                __nv_bfloat162 h23 = __floats2bfloat162_rn(v.z, v.w);
                __nv_bfloat162 l01 = __floats2bfloat162_rn(v.x - __bfloat162float(h01.x),
                                                           v.y - __bfloat162float(h01.y));
                __nv_bfloat162 l23 = __floats2bfloat162_rn(v.z - __bfloat162float(h23.x),
                                                           v.w - __bfloat162float(h23.y));
                *(uint2*)(sm + base + AH + boff) = make_uint2(*(uint32_t*)&h01, *(uint32_t*)&h23);
                *(uint2*)(sm + base + AL + boff) = make_uint2(*(uint32_t*)&l01, *(uint32_t*)&l23);
            }
            {
                float4 v = rw[j];
                __nv_bfloat162 h01 = __floats2bfloat162_rn(v.x, v.y);
                __nv_bfloat162 h23 = __floats2bfloat162_rn(v.z, v.w);
                __nv_bfloat162 l01 = __floats2bfloat162_rn(v.x - __bfloat162float(h01.x),
                                                           v.y - __bfloat162float(h01.y));
                __nv_bfloat162 l23 = __floats2bfloat162_rn(v.z - __bfloat162float(h23.x),
                                                           v.w - __bfloat162float(h23.y));
                *(uint2*)(sm + base + WH + boff) = make_uint2(*(uint32_t*)&h01, *(uint32_t*)&h23);
                *(uint2*)(sm + base + WL + boff) = make_uint2(*(uint32_t*)&l01, *(uint32_t*)&l23);
            }
        }
        __syncthreads();   // single sync per iter (ping-pong buffers)

        // ---- issue next-chunk LDGs; latency hidden under MMA below ----
        if (c + 1 < NCH) {
            int k0 = (c + 1) * 32;
#pragma unroll
            for (int j = 0; j < 4; j++) {
                int idx = tid + j * 256;
                int r = idx >> 3, q = idx & 7;
                int gr = bm + r;
                ra[j] = (gr < M) ? *(const float4*)(Ag + (size_t)gr * D_IN + k0 + q * 4)
                                 : make_float4(0.f, 0.f, 0.f, 0.f);
                rw[j] = *(const float4*)(Wg + (size_t)(bn + r) * D_IN + k0 + q * 4);
            }
        }

        // ---- compute on buffer c&1: 2 k16 steps ----
        const uint32_t sAH = smb + base + AH;
        const uint32_t sAL = smb + base + AL;
        const uint32_t sWH = smb + base + WH;
        const uint32_t sWL = smb + base + WL;
#pragma unroll
        for (int kk = 0; kk < 2; kk++) {
            uint32_t ah[2][4], al[2][4], bh[4][4], bl[4][4];
#pragma unroll
            for (int mt = 0; mt < 2; mt++) {
                int r = warp_m + mt * 16 + (lane & 15);
                int cc = kk * 16 + (lane >> 4) * 8;
                uint32_t off = (uint32_t)(r * LDS + cc) * 2;
                ldm_x4(ah[mt], sAH + off);
                ldm_x4(al[mt], sAL + off);
            }
#pragma unroll
            for (int nt2 = 0; nt2 < 4; nt2++) {
                int r = warp_n + nt2 * 16 + ((lane >> 4) ? 8 : 0) + (lane & 7);
                int cc = kk * 16 + ((lane >> 3) & 1) * 8;
                uint32_t off = (uint32_t)(r * LDS + cc) * 2;
                ldm_x4(bh[nt2], sWH + off);
                ldm_x4(bl[nt2], sWL + off);
            }
#pragma unroll
            for (int mt = 0; mt < 2; mt++)
#pragma unroll
                for (int nt = 0; nt < 8; nt++) {
                    const uint32_t* pbh = &bh[nt >> 1][(nt & 1) * 2];
                    const uint32_t* pbl = &bl[nt >> 1][(nt & 1) * 2];
                    mma_bf16(acc[mt][nt], ah[mt], pbh);
                    mma_bf16(acc[mt][nt], ah[mt], pbl);
                    mma_bf16(acc[mt][nt], al[mt], pbh);
                }
        }
    }

    // ---- epilogue: bias + tanh + fused row-norm partials ----
    float rs[2][2] = {{0.f, 0.f}, {0.f, 0.f}};
#pragma unroll
    for (int mt = 0; mt < 2; mt++) {
        int r0 = bm + warp_m + mt * 16 + (lane >> 2);
#pragma unroll
        for (int nt = 0; nt < 8; nt++) {
            int gc = bn + warp_n + nt * 8 + (lane & 3) * 2;
            float b0 = bias[gc], b1 = bias[gc + 1];
            if (r0 < M) {
                float t0 = tanhf(acc[mt][nt][0] + b0);
                float t1 = tanhf(acc[mt][nt][1] + b1);
                C[(size_t)r0 * HD + gc]     = t0;
                C[(size_t)r0 * HD + gc + 1] = t1;
                rs[mt][0] = fmaf(t0, t0, fmaf(t1, t1, rs[mt][0]));
            }
            if (r0 + 8 < M) {
                float t2 = tanhf(acc[mt][nt][2] + b0);
                float t3 = tanhf(acc[mt][nt][3] + b1);
                C[(size_t)(r0 + 8) * HD + gc]     = t2;
                C[(size_t)(r0 + 8) * HD + gc + 1] = t3;
                rs[mt][1] = fmaf(t2, t2, fmaf(t3, t3, rs[mt][1]));
            }
        }
    }
#pragma unroll
    for (int mt = 0; mt < 2; mt++)
#pragma unroll
        for (int h = 0; h < 2; h++) {
            float v = rs[mt][h];
            v += __shfl_xor_sync(0xffffffffu, v, 1);
            v += __shfl_xor_sync(0xffffffffu, v, 2);
            int row = bm + warp_m + mt * 16 + (lane >> 2) + h * 8;
            if ((lane & 3) == 0 && row < M) atomicAdd(&N2[row], v);
        }
}

// ---------------------------------------------------------------------------
// s[k] = wa[k] / max(sqrt(kn2[k]), 1e-12)   (norms already computed in GEMM)
__global__ void k_scale_kernel(const float* __restrict__ wa_w) {
    int k = blockIdx.x * 256 + threadIdx.x;
    if (k < NK) g_s[k] = wa_w[k] / fmaxf(sqrtf(g_kn2[k]), 1e-12f);
}

// v[h] = sum_k s[k] * kt[k][h] — coalesced float4 column-slab reduction
__global__ void v_accum_kernel() {
    int c4   = threadIdx.x & 127;        // float4 column
    int half = threadIdx.x >> 7;
    int k0   = blockIdx.x * 64 + half * 32;
    float4 acc = make_float4(0.f, 0.f, 0.f, 0.f);
    for (int i = 0; i < 32; i++) {
        int k = k0 + i;
        if (k >= NK) break;
        float s = g_s[k];
        float4 kv = *(const float4*)(g_kt + (size_t)k * HD + c4 * 4);
        acc.x = fmaf(s, kv.x, acc.x);
        acc.y = fmaf(s, kv.y, acc.y);
        acc.z = fmaf(s, kv.z, acc.z);
        acc.w = fmaf(s, kv.w, acc.w);
    }
    atomicAdd(&g_v[c4 * 4 + 0], acc.x);
    atomicAdd(&g_v[c4 * 4 + 1], acc.y);
    atomicAdd(&g_v[c4 * 4 + 2], acc.z);
    atomicAdd(&g_v[c4 * 4 + 3], acc.w);
}

// A1[q] = dot(qt_q, v)/max(sqrt(qn2[q]),eps) + wa_b  — float4 loads
__global__ void a1_kernel(const float* __restrict__ wa_b) {
    int row  = blockIdx.x * 8 + (threadIdx.x >> 5);
    int lane = threadIdx.x & 31;
    const float4* qr = (const float4*)(g_qt + (size_t)row * HD);
    const float4* vv = (const float4*)g_v;
    float dot = 0.f;
#pragma unroll
    for (int j = 0; j < 4; j++) {
        float4 a = qr[lane + 32 * j];
        float4 b = vv[lane + 32 * j];
        dot = fmaf(a.x, b.x, fmaf(a.y, b.y, fmaf(a.z, b.z, fmaf(a.w, b.w, dot))));
    }
#pragma unroll
    for (int o = 16; o > 0; o >>= 1) dot += __shfl_xor_sync(0xffffffffu, dot, o);
    if (lane == 0)
        g_A1[row] = dot / fmaxf(sqrtf(g_qn2[row]), 1e-12f) + wa_b[0];
}

// ---------------------------------------------------------------------------
// Exact k-th order statistic via 3-level radix select + global max.
// ---------------------------------------------------------------------------
__device__ __forceinline__ uint32_t f2ord(float f) {
    uint32_t u = __float_as_uint(f);
    return u ^ ((u >> 31) ? 0xFFFFFFFFu : 0x80000000u);
}
__device__ __forceinline__ float ord2f(uint32_t u) {
    u ^= ((u >> 31) ? 0x80000000u : 0xFFFFFFFFu);
    return __uint_as_float(u);
}

__global__ void select_kernel() {
    __shared__ uint32_t hist[2048];
    __shared__ uint32_t wred[32];
    __shared__ uint32_t s_bin, s_base;
    __shared__ float s_max;
    const int t = threadIdx.x;
    const int lane = t & 31, w = t >> 5;

    float mx = -INFINITY;
    for (int i = t; i < NQ; i += 1024) mx = fmaxf(mx, g_A1[i]);
#pragma unroll
    for (int o = 16; o > 0; o >>= 1) mx = fmaxf(mx, __shfl_xor_sync(0xffffffffu, mx, o));
    if (lane == 0) wred[w] = __float_as_uint(mx);
    __syncthreads();
    if (w == 0) {
        float m = __uint_as_float(wred[lane]);
#pragma unroll
        for (int o = 16; o > 0; o >>= 1) m = fmaxf(m, __shfl_xor_sync(0xffffffffu, m, o));
        if (lane == 0) s_max = m;
    }
    __syncthreads();

    uint32_t k = THRE_IDX;
    uint32_t prefix = 0, pmask = 0;
    const int shifts[3] = {21, 10, 0};
    const uint32_t widths[3] = {2048, 2048, 1024};

    for (int lev = 0; lev < 3; lev++) {
        const int sh = shifts[lev];
        const uint32_t width = widths[lev];
        const uint32_t bmask = width - 1;
        hist[t] = 0; hist[t + 1024] = 0;
        __syncthreads();
        for (int i = t; i < NQ; i += 1024) {
            uint32_t key = f2ord(g_A1[i]);
            if ((key & pmask) == prefix)
                atomicAdd(&hist[(key >> sh) & bmask], 1u);
        }
        __syncthreads();
        uint32_t c0 = (2u * t     < width) ? hist[2 * t]     : 0u;
        uint32_t c1 = (2u * t + 1 < width) ? hist[2 * t + 1] : 0u;
        uint32_t tsum = c0 + c1;
        uint32_t inc = tsum;
#pragma unroll
        for (int o = 1; o < 32; o <<= 1) {
            uint32_t v = __shfl_up_sync(0xffffffffu, inc, o);
            if (lane >= o) inc += v;
        }
        if (lane == 31) wred[w] = inc;
        __syncthreads();
        if (w == 0) {
            uint32_t v = wred[lane];
            uint32_t winc = v;
#pragma unroll
            for (int o = 1; o < 32; o <<= 1) {
                uint32_t x = __shfl_up_sync(0xffffffffu, winc, o);
                if (lane >= o) winc += x;
            }
            wred[lane] = winc - v;   // exclusive
        }
        __syncthreads();
        uint32_t ex = wred[w] + (inc - tsum);
        if (k >= ex && k < ex + c0)             { s_bin = 2 * t;     s_base = ex; }
        else if (k >= ex + c0 && k < ex + tsum) { s_bin = 2 * t + 1; s_base = ex + c0; }
        __syncthreads();
        uint32_t bin = s_bin;
        k -= s_base;
        prefix |= (bin << sh);
        pmask  |= (bmask << sh);
        __syncthreads();
    }
    if (t == 0) {
        g_thre = ord2f(prefix);
        g_m = fmaxf(s_max, 0.f);
    }
}

// ---------------------------------------------------------------------------
__global__ void zdenom_kernel() {
    __shared__ float red[8];
    int q = blockIdx.x * 256 + threadIdx.x;
    float a = g_A1[q];
    float tt = (a > g_thre) ? a : 0.f;
    float e = expf(tt - g_m);
#pragma unroll
    for (int o = 16; o > 0; o >>= 1) e += __shfl_xor_sync(0xffffffffu, e, o);
    int lane = threadIdx.x & 31, w = threadIdx.x >> 5;
    if (lane == 0) red[w] = e;
    __syncthreads();
    if (w == 0) {
        float s = (lane < 8) ? red[lane] : 0.f;
#pragma unroll
        for (int o = 4; o > 0; o >>= 1) s += __shfl_xor_sync(0xffffffffu, s, o);
        if (lane == 0) atomicAdd(&g_Z, s);
    }
}

__global__ void attn_kernel(float* __restrict__ out) {
    int q = blockIdx.x * 256 + threadIdx.x;
    float a = g_A1[q];
    float tt = (a > g_thre) ? a : 0.f;
    out[1 + q] = expf(tt - g_m) / g_Z;
}

// z[h] = sum_q attn[q]*qt[q][h] — coalesced float4 column-slab reduction
__global__ void z_accum_kernel(const float* __restrict__ out) {
    int c4   = threadIdx.x & 127;
    int half = threadIdx.x >> 7;
    int q0   = blockIdx.x * 128 + half * 64;
    float4 acc = make_float4(0.f, 0.f, 0.f, 0.f);
    for (int i = 0; i < 64; i++) {
        int q = q0 + i;
        float a = out[1 + q];
        float4 qv = *(const float4*)(g_qt + (size_t)q * HD + c4 * 4);
        acc.x = fmaf(a, qv.x, acc.x);
        acc.y = fmaf(a, qv.y, acc.y);
        acc.z = fmaf(a, qv.z, acc.z);
        acc.w = fmaf(a, qv.w, acc.w);
    }
    atomicAdd(&g_z[c4 * 4 + 0], acc.x);
    atomicAdd(&g_z[c4 * 4 + 1], acc.y);
    atomicAdd(&g_z[c4 * 4 + 2], acc.z);
    atomicAdd(&g_z[c4 * 4 + 3], acc.w);
}

__global__ void final_kernel(const float* __restrict__ cls_w,
                             const float* __restrict__ cls_b,
                             float* __restrict__ out) {
    __shared__ float red[16];
    int t = threadIdx.x;
    float p = g_z[t] * cls_w[t];
#pragma unroll
    for (int o = 16; o > 0; o >>= 1) p += __shfl_xor_sync(0xffffffffu, p, o);
    int lane = t & 31, w = t >> 5;
    if (lane == 0) red[w] = p;
    __syncthreads();
    if (w == 0) {
        float s = (lane < 16) ? red[lane] : 0.f;
#pragma unroll
        for (int o = 8; o > 0; o >>= 1) s += __shfl_xor_sync(0xffffffffu, s, o);
        if (lane == 0) out[0] = s + cls_b[0];
    }
}

// ---------------------------------------------------------------------------
extern "C" void kernel_launch(void* const* d_in, const int* in_sizes, int n_in,
                              void* d_out, int out_size) {
    const float* query = (const float*)d_in[0];
    const float* key_x = (const float*)d_in[1];
    const float* wq_w  = (const float*)d_in[2];
    const float* wq_b  = (const float*)d_in[3];
    const float* wk_w  = (const float*)d_in[4];
    const float* wk_b  = (const float*)d_in[5];
    const float* wa_w  = (const float*)d_in[6];
    const float* wa_b  = (const float*)d_in[7];
    const float* cls_w = (const float*)d_in[8];
    const float* cls_b = (const float*)d_in[9];
    float* out = (float*)d_out;

    static bool attr_set = false;
    if (!attr_set) {
        cudaFuncSetAttribute(gemm_tc_kernel,
                             cudaFuncAttributeMaxDynamicSharedMemorySize, GEMM_SMEM);
        attr_set = true;
    }

    init_kernel<<<(NQ + 255) / 256, 256>>>();

    // Fused q+k projection GEMMs: grid y = 128 (q) + 62 (k) blocks
    dim3 gg(HD / 128, 128 + (NK + 127) / 128);
    gemm_tc_kernel<<<gg, 256, GEMM_SMEM>>>(query, wq_w, wq_b, key_x, wk_w, wk_b);

    k_scale_kernel<<<(NK + 255) / 256, 256>>>(wa_w);
    v_accum_kernel<<<(NK + 63) / 64, 256>>>();
    a1_kernel<<<NQ / 8, 256>>>(wa_b);
    select_kernel<<<1, 1024>>>();
    zdenom_kernel<<<NQ / 256, 256>>>();
    attn_kernel<<<NQ / 256, 256>>>(out);
    z_accum_kernel<<<NQ / 128, 256>>>(out);
    final_kernel<<<1, 512>>>(cls_w, cls_b, out);
}